// round 8
// baseline (speedup 1.0000x reference)
#include <cuda_runtime.h>

#define NT 512

__device__ __forceinline__ int reflect512(int i) {
    i = (i < 0) ? -i : i;
    return (i > 511) ? 1022 - i : i;
}
__device__ __forceinline__ int clamp511(int i) {
    return min(max(i, 0), 511);
}
__device__ __forceinline__ float grayf(const float* __restrict__ base, int off) {
    float r = base[off], g = base[off + 262144], b = base[off + 524288];
    return fmaf(0.1495f, r, fmaf(0.2935f, g, fmaf(0.057f, b, 0.5f)));
}
__device__ __forceinline__ int octclass(float gx, float gy) {
    const float T = 0.41421356237309503f;  // tan(22.5 deg)
    float ax = fabsf(gx), ay = fabsf(gy);
    if (ay <= T * ax) return 0;
    if (ax <= T * ay) return 2;
    return ((__float_as_int(gx) ^ __float_as_int(gy)) >= 0) ? 1 : 3;
}
__device__ __forceinline__ float magf(float gx, float gy) {
    return sqrtf(fmaf(gx, gx, fmaf(gy, gy, 1e-6f)));
}

__global__ __launch_bounds__(NT)
void canny_fused_kernel(const float* __restrict__ in, float* __restrict__ out)
{
    // 64x32 output tile. All row strides = 76 floats (rows 16B aligned).
    //   poolA: sg[40][76] (gray, cols 0..71 valid) -> sb[36][76] (blur, cols 0..67 valid)
    //   poolB: th[40][76] (hblur, cols 0..67 valid) -> smg[34][76] (mag, cols 1..66 valid)
    __shared__ __align__(16) float poolA[40 * 76];
    __shared__ __align__(16) float poolB[40 * 76];
    __shared__ __align__(16) unsigned char sclbuf[34 * 76];

    float (*sg)[76]  = reinterpret_cast<float(*)[76]>(poolA);
    float (*sb)[76]  = reinterpret_cast<float(*)[76]>(poolA);
    float (*th)[76]  = reinterpret_cast<float(*)[76]>(poolB);
    float (*smg)[76] = reinterpret_cast<float(*)[76]>(poolB);
    unsigned char (*scl)[76] = reinterpret_cast<unsigned char(*)[76]>(sclbuf);

    const int tid = threadIdx.x;
    const int bx0 = blockIdx.x * 64, by0 = blockIdx.y * 32;
    const float* base = in + (size_t)blockIdx.z * 786432u;
    const float w0 = 0.054488685f, w1 = 0.24420134f, w2 = 0.40261995f;

    const bool reflX = (blockIdx.x == 0u) | (blockIdx.x == 7u);
    const bool reflY = (blockIdx.y == 0u) | (blockIdx.y == 15u);

    // ---- stage 1: gray 40 rows x 72 cols (18 float4 groups = 720 items) ----
    if (!(reflX | reflY)) {
        #pragma unroll
        for (int k = 0; k < 2; k++) {
            int u = tid + k * NT;
            if (u < 720) {
                int ly = u / 18, g = u - ly * 18;
                int off = (by0 - 4 + ly) * 512 + (bx0 - 4) + 4 * g;
                float4 r  = *(const float4*)(base + off);
                float4 gg = *(const float4*)(base + off + 262144);
                float4 bb = *(const float4*)(base + off + 524288);
                float4 o;
                o.x = fmaf(0.1495f, r.x, fmaf(0.2935f, gg.x, fmaf(0.057f, bb.x, 0.5f)));
                o.y = fmaf(0.1495f, r.y, fmaf(0.2935f, gg.y, fmaf(0.057f, bb.y, 0.5f)));
                o.z = fmaf(0.1495f, r.z, fmaf(0.2935f, gg.z, fmaf(0.057f, bb.z, 0.5f)));
                o.w = fmaf(0.1495f, r.w, fmaf(0.2935f, gg.w, fmaf(0.057f, bb.w, 0.5f)));
                *(float4*)&sg[ly][4 * g] = o;
            }
        }
    } else {
        for (int u = tid; u < 40 * 72; u += NT) {
            int ly = u / 72, lx = u - ly * 72;
            int ay = by0 - 4 + ly, ax = bx0 - 4 + lx;
            float g = 0.0f;
            if ((unsigned)ay < 512u && (unsigned)ax < 512u) g = grayf(base, ay * 512 + ax);
            sg[ly][lx] = g;
        }
    }
    __syncthreads();

    // ---- stage 2: horizontal blur, 40 x 18 groups = 720 items ----
    if (!reflX) {
        #pragma unroll
        for (int k = 0; k < 2; k++) {
            int u = tid + k * NT;
            if (u < 720) {
                int ly = u / 18, g = u - ly * 18;
                float4 v0 = *(const float4*)&sg[ly][4 * g];
                float4 v1 = *(const float4*)&sg[ly][4 * g + 4];
                float4 o;
                o.x = w0 * (v0.x + v1.x) + w1 * (v0.y + v0.w) + w2 * v0.z;
                o.y = w0 * (v0.y + v1.y) + w1 * (v0.z + v1.x) + w2 * v0.w;
                o.z = w0 * (v0.z + v1.z) + w1 * (v0.w + v1.y) + w2 * v1.x;
                o.w = w0 * (v0.w + v1.w) + w1 * (v1.x + v1.z) + w2 * v1.y;
                *(float4*)&th[ly][4 * g] = o;
            }
        }
    } else {
        const int ox = bx0 - 4;
        for (int u = tid; u < 40 * 68; u += NT) {
            int ly = u / 68, j = u - ly * 68;
            int cx = clamp511(bx0 - 2 + j);
            th[ly][j] = w0 * (sg[ly][reflect512(cx - 2) - ox] + sg[ly][reflect512(cx + 2) - ox])
                      + w1 * (sg[ly][reflect512(cx - 1) - ox] + sg[ly][reflect512(cx + 1) - ox])
                      + w2 * sg[ly][reflect512(cx) - ox];
        }
    }
    __syncthreads();

    // ---- stage 3: vertical blur -> sb rows 0..35 (aliases sg); 648 items ----
    #pragma unroll
    for (int k = 0; k < 2; k++) {
        int u = tid + k * NT;
        if (u < 648) {
            int i = u / 18, g = u - i * 18;
            int r0, r1, r2, r3, r4;
            if (!reflY) { r0 = i; r1 = i + 1; r2 = i + 2; r3 = i + 3; r4 = i + 4; }
            else {
                int cy = clamp511(by0 - 2 + i), oy = by0 - 4;
                r0 = reflect512(cy - 2) - oy; r1 = reflect512(cy - 1) - oy;
                r2 = reflect512(cy) - oy;
                r3 = reflect512(cy + 1) - oy; r4 = reflect512(cy + 2) - oy;
            }
            float4 a = *(const float4*)&th[r0][4 * g];
            float4 b = *(const float4*)&th[r1][4 * g];
            float4 c = *(const float4*)&th[r2][4 * g];
            float4 d = *(const float4*)&th[r3][4 * g];
            float4 e = *(const float4*)&th[r4][4 * g];
            float4 o;
            o.x = w0 * (a.x + e.x) + w1 * (b.x + d.x) + w2 * c.x;
            o.y = w0 * (a.y + e.y) + w1 * (b.y + d.y) + w2 * c.y;
            o.z = w0 * (a.z + e.z) + w1 * (b.z + d.z) + w2 * c.z;
            o.w = w0 * (a.w + e.w) + w1 * (b.w + d.w) + w2 * c.w;
            *(float4*)&sb[i][4 * g] = o;
        }
    }
    __syncthreads();

    // ---- stage 4: Sobel + magnitude + class -> smg (aliases th), scl; 612 items ----
    #pragma unroll
    for (int k = 0; k < 2; k++) {
        int u = tid + k * NT;
        if (u < 612) {
            int i = u / 18, g = u - i * 18;
            int cm = max(4 * g - 1, 0);
            float  m0 = sb[i    ][cm];
            float4 v0 = *(const float4*)&sb[i    ][4 * g];
            float  p0 = sb[i    ][4 * g + 4];
            float  m1 = sb[i + 1][cm];
            float4 v1 = *(const float4*)&sb[i + 1][4 * g];
            float  p1 = sb[i + 1][4 * g + 4];
            float  m2 = sb[i + 2][cm];
            float4 v2 = *(const float4*)&sb[i + 2][4 * g];
            float  p2 = sb[i + 2][4 * g + 4];

            float4 mg; uchar4 cc;
            {   // t=0
                float gx = (v0.y - m0) + 2.0f * (v1.y - m1) + (v2.y - m2);
                float gy = (m2 - m0) + 2.0f * (v2.x - v0.x) + (v2.y - v0.y);
                mg.x = magf(gx, gy); cc.x = (unsigned char)octclass(gx, gy);
            }
            {   // t=1
                float gx = (v0.z - v0.x) + 2.0f * (v1.z - v1.x) + (v2.z - v2.x);
                float gy = (v2.x - v0.x) + 2.0f * (v2.y - v0.y) + (v2.z - v0.z);
                mg.y = magf(gx, gy); cc.y = (unsigned char)octclass(gx, gy);
            }
            {   // t=2
                float gx = (v0.w - v0.y) + 2.0f * (v1.w - v1.y) + (v2.w - v2.y);
                float gy = (v2.y - v0.y) + 2.0f * (v2.z - v0.z) + (v2.w - v0.w);
                mg.z = magf(gx, gy); cc.z = (unsigned char)octclass(gx, gy);
            }
            {   // t=3
                float gx = (p0 - v0.z) + 2.0f * (p1 - v1.z) + (p2 - v2.z);
                float gy = (v2.z - v0.z) + 2.0f * (v2.w - v0.w) + (p2 - p0);
                mg.w = magf(gx, gy); cc.w = (unsigned char)octclass(gx, gy);
            }
            *(float4*)&smg[i][4 * g] = mg;
            *(uchar4*)&scl[i][4 * g] = cc;
        }
    }
    __syncthreads();

    // ---- stage 5: NMS + store, 512 items (1/thread): 32 rows x 16 groups of 4 px ----
    const unsigned DY = 0x0001u, DX = 0x0122u;
    const bool border = reflX | reflY;

    {
        int u = tid;
        int iy = u >> 4, g = u & 15;
        int ii = iy + 1;
        int j0 = 4 * g + 2;

        float2 ca = *(const float2*)&smg[ii][j0];
        float2 cb = *(const float2*)&smg[ii][j0 + 2];
        uchar2 ka = *(const uchar2*)&scl[ii][j0];
        uchar2 kb = *(const uchar2*)&scl[ii][j0 + 2];
        float mcv[4] = {ca.x, ca.y, cb.x, cb.y};
        int   cls[4] = {ka.x, ka.y, kb.x, kb.y};

        float4 res;
        float* rp = &res.x;
        #pragma unroll
        for (int t = 0; t < 4; t++) {
            int s  = cls[t] * 4;
            int dy = (int)((DY >> s) & 0xFu) - 1;
            int dx = (int)((DX >> s) & 0xFu) - 1;
            int jj = j0 + t;
            float mp = smg[ii + dy][jj + dx];
            float mq = smg[ii - dy][jj - dx];
            if (border) {
                int ay = by0 + iy, ax = bx0 + 4 * g + t;
                if (!((unsigned)(ay + dy) < 512u && (unsigned)(ax + dx) < 512u)) mp = 0.0f;
                if (!((unsigned)(ay - dy) < 512u && (unsigned)(ax - dx) < 512u)) mq = 0.0f;
            }
            float m = mcv[t];
            rp[t] = (m > mp && m > mq) ? m : 0.0f;
        }
        *(float4*)&out[((size_t)blockIdx.z * 512 + by0 + iy) * 512 + bx0 + 4 * g] = res;
    }
}

extern "C" void kernel_launch(void* const* d_in, const int* in_sizes, int n_in,
                              void* d_out, int out_size)
{
    (void)in_sizes; (void)n_in; (void)out_size;
    const float* data = (const float*)d_in[0];
    float* out = (float*)d_out;

    dim3 grid(8, 16, 16);
    dim3 block(NT);
    canny_fused_kernel<<<grid, block>>>(data, out);
}

// round 9
// speedup vs baseline: 1.0653x; 1.0653x over previous
#include <cuda_runtime.h>

#define NT 256

__device__ __forceinline__ int reflect512(int i) {
    i = (i < 0) ? -i : i;
    return (i > 511) ? 1022 - i : i;
}
__device__ __forceinline__ int clamp511(int i) {
    return min(max(i, 0), 511);
}
__device__ __forceinline__ float grayf(const float* __restrict__ base, int off) {
    float r = base[off], g = base[off + 262144], b = base[off + 524288];
    return fmaf(0.1495f, r, fmaf(0.2935f, g, fmaf(0.057f, b, 0.5f)));
}
__device__ __forceinline__ int octclass(float gx, float gy) {
    const float T = 0.41421356237309503f;  // tan(22.5 deg)
    float ax = fabsf(gx), ay = fabsf(gy);
    if (ay <= T * ax) return 0;
    if (ax <= T * ay) return 2;
    return ((__float_as_int(gx) ^ __float_as_int(gy)) >= 0) ? 1 : 3;
}
// sqrt(x) with no MUFU: bit-hack rsqrt + 2 Newton iterations (all FMA pipe).
// x >= 1e-6 always (eps), so no zero/denormal concerns.
__device__ __forceinline__ float fast_sqrt(float x) {
    float y = __int_as_float(0x5f3759df - (__float_as_int(x) >> 1));
    y = y * fmaf(-0.5f * x, y * y, 1.5f);
    y = y * fmaf(-0.5f * x, y * y, 1.5f);
    return x * y;
}

__global__ __launch_bounds__(NT)
void canny_fused_kernel(const float* __restrict__ in, float* __restrict__ out)
{
    // 64x32 output tile. All row strides = 76 floats (rows 16B aligned).
    //   poolA: sg[40][76] (gray, cols 0..71 valid) -> sb[36][76] (blur, cols 0..67 valid)
    //   poolB: th[40][76] (hblur, cols 0..67 valid) -> smg[34][76] (SQUARED mag, cols 1..66 valid)
    __shared__ __align__(16) float poolA[40 * 76];
    __shared__ __align__(16) float poolB[40 * 76];
    __shared__ __align__(16) unsigned char sclbuf[34 * 76];

    float (*sg)[76]  = reinterpret_cast<float(*)[76]>(poolA);
    float (*sb)[76]  = reinterpret_cast<float(*)[76]>(poolA);
    float (*th)[76]  = reinterpret_cast<float(*)[76]>(poolB);
    float (*smg)[76] = reinterpret_cast<float(*)[76]>(poolB);
    unsigned char (*scl)[76] = reinterpret_cast<unsigned char(*)[76]>(sclbuf);

    const int tid = threadIdx.x;
    const int bx0 = blockIdx.x * 64, by0 = blockIdx.y * 32;
    const float* base = in + (size_t)blockIdx.z * 786432u;
    const float w0 = 0.054488685f, w1 = 0.24420134f, w2 = 0.40261995f;

    const bool reflX = (blockIdx.x == 0u) | (blockIdx.x == 7u);
    const bool reflY = (blockIdx.y == 0u) | (blockIdx.y == 15u);

    // ---- stage 1: gray 40 rows x 72 cols (18 float4 groups = 720 items) ----
    if (!(reflX | reflY)) {
        #pragma unroll
        for (int k = 0; k < 3; k++) {
            int u = tid + k * NT;
            if (u < 720) {
                int ly = u / 18, g = u - ly * 18;
                int off = (by0 - 4 + ly) * 512 + (bx0 - 4) + 4 * g;
                float4 r  = *(const float4*)(base + off);
                float4 gg = *(const float4*)(base + off + 262144);
                float4 bb = *(const float4*)(base + off + 524288);
                float4 o;
                o.x = fmaf(0.1495f, r.x, fmaf(0.2935f, gg.x, fmaf(0.057f, bb.x, 0.5f)));
                o.y = fmaf(0.1495f, r.y, fmaf(0.2935f, gg.y, fmaf(0.057f, bb.y, 0.5f)));
                o.z = fmaf(0.1495f, r.z, fmaf(0.2935f, gg.z, fmaf(0.057f, bb.z, 0.5f)));
                o.w = fmaf(0.1495f, r.w, fmaf(0.2935f, gg.w, fmaf(0.057f, bb.w, 0.5f)));
                *(float4*)&sg[ly][4 * g] = o;
            }
        }
    } else {
        for (int u = tid; u < 40 * 72; u += NT) {
            int ly = u / 72, lx = u - ly * 72;
            int ay = by0 - 4 + ly, ax = bx0 - 4 + lx;
            float g = 0.0f;
            if ((unsigned)ay < 512u && (unsigned)ax < 512u) g = grayf(base, ay * 512 + ax);
            sg[ly][lx] = g;
        }
    }
    __syncthreads();

    // ---- stage 2: horizontal blur, 40 x 18 groups = 720 items ----
    if (!reflX) {
        #pragma unroll
        for (int k = 0; k < 3; k++) {
            int u = tid + k * NT;
            if (u < 720) {
                int ly = u / 18, g = u - ly * 18;
                float4 v0 = *(const float4*)&sg[ly][4 * g];
                float4 v1 = *(const float4*)&sg[ly][4 * g + 4];
                float4 o;
                o.x = w0 * (v0.x + v1.x) + w1 * (v0.y + v0.w) + w2 * v0.z;
                o.y = w0 * (v0.y + v1.y) + w1 * (v0.z + v1.x) + w2 * v0.w;
                o.z = w0 * (v0.z + v1.z) + w1 * (v0.w + v1.y) + w2 * v1.x;
                o.w = w0 * (v0.w + v1.w) + w1 * (v1.x + v1.z) + w2 * v1.y;
                *(float4*)&th[ly][4 * g] = o;
            }
        }
    } else {
        const int ox = bx0 - 4;
        for (int u = tid; u < 40 * 68; u += NT) {
            int ly = u / 68, j = u - ly * 68;
            int cx = clamp511(bx0 - 2 + j);
            th[ly][j] = w0 * (sg[ly][reflect512(cx - 2) - ox] + sg[ly][reflect512(cx + 2) - ox])
                      + w1 * (sg[ly][reflect512(cx - 1) - ox] + sg[ly][reflect512(cx + 1) - ox])
                      + w2 * sg[ly][reflect512(cx) - ox];
        }
    }
    __syncthreads();

    // ---- stage 3: vertical blur -> sb rows 0..35 (aliases sg); 648 items ----
    #pragma unroll
    for (int k = 0; k < 3; k++) {
        int u = tid + k * NT;
        if (u < 648) {
            int i = u / 18, g = u - i * 18;
            int r0, r1, r2, r3, r4;
            if (!reflY) { r0 = i; r1 = i + 1; r2 = i + 2; r3 = i + 3; r4 = i + 4; }
            else {
                int cy = clamp511(by0 - 2 + i), oy = by0 - 4;
                r0 = reflect512(cy - 2) - oy; r1 = reflect512(cy - 1) - oy;
                r2 = reflect512(cy) - oy;
                r3 = reflect512(cy + 1) - oy; r4 = reflect512(cy + 2) - oy;
            }
            float4 a = *(const float4*)&th[r0][4 * g];
            float4 b = *(const float4*)&th[r1][4 * g];
            float4 c = *(const float4*)&th[r2][4 * g];
            float4 d = *(const float4*)&th[r3][4 * g];
            float4 e = *(const float4*)&th[r4][4 * g];
            float4 o;
            o.x = w0 * (a.x + e.x) + w1 * (b.x + d.x) + w2 * c.x;
            o.y = w0 * (a.y + e.y) + w1 * (b.y + d.y) + w2 * c.y;
            o.z = w0 * (a.z + e.z) + w1 * (b.z + d.z) + w2 * c.z;
            o.w = w0 * (a.w + e.w) + w1 * (b.w + d.w) + w2 * c.w;
            *(float4*)&sb[i][4 * g] = o;
        }
    }
    __syncthreads();

    // ---- stage 4: Sobel + SQUARED magnitude + class -> smg (aliases th), scl; 612 items ----
    #pragma unroll
    for (int k = 0; k < 3; k++) {
        int u = tid + k * NT;
        if (u < 612) {
            int i = u / 18, g = u - i * 18;
            int cm = max(4 * g - 1, 0);
            float  m0 = sb[i    ][cm];
            float4 v0 = *(const float4*)&sb[i    ][4 * g];
            float  p0 = sb[i    ][4 * g + 4];
            float  m1 = sb[i + 1][cm];
            float4 v1 = *(const float4*)&sb[i + 1][4 * g];
            float  p1 = sb[i + 1][4 * g + 4];
            float  m2 = sb[i + 2][cm];
            float4 v2 = *(const float4*)&sb[i + 2][4 * g];
            float  p2 = sb[i + 2][4 * g + 4];

            float4 mg; uchar4 cc;
            {   // t=0
                float gx = (v0.y - m0) + 2.0f * (v1.y - m1) + (v2.y - m2);
                float gy = (m2 - m0) + 2.0f * (v2.x - v0.x) + (v2.y - v0.y);
                mg.x = fmaf(gx, gx, fmaf(gy, gy, 1e-6f)); cc.x = (unsigned char)octclass(gx, gy);
            }
            {   // t=1
                float gx = (v0.z - v0.x) + 2.0f * (v1.z - v1.x) + (v2.z - v2.x);
                float gy = (v2.x - v0.x) + 2.0f * (v2.y - v0.y) + (v2.z - v0.z);
                mg.y = fmaf(gx, gx, fmaf(gy, gy, 1e-6f)); cc.y = (unsigned char)octclass(gx, gy);
            }
            {   // t=2
                float gx = (v0.w - v0.y) + 2.0f * (v1.w - v1.y) + (v2.w - v2.y);
                float gy = (v2.y - v0.y) + 2.0f * (v2.z - v0.z) + (v2.w - v0.w);
                mg.z = fmaf(gx, gx, fmaf(gy, gy, 1e-6f)); cc.z = (unsigned char)octclass(gx, gy);
            }
            {   // t=3
                float gx = (p0 - v0.z) + 2.0f * (p1 - v1.z) + (p2 - v2.z);
                float gy = (v2.z - v0.z) + 2.0f * (v2.w - v0.w) + (p2 - p0);
                mg.w = fmaf(gx, gx, fmaf(gy, gy, 1e-6f)); cc.w = (unsigned char)octclass(gx, gy);
            }
            *(float4*)&smg[i][4 * g] = mg;
            *(uchar4*)&scl[i][4 * g] = cc;
        }
    }
    __syncthreads();

    // ---- stage 5: NMS on squared magnitudes (exact) + sqrt only for output ----
    const unsigned DY = 0x0001u, DX = 0x0122u;
    const bool border = reflX | reflY;

    #pragma unroll
    for (int k = 0; k < 2; k++) {
        int u = tid + k * NT;
        int iy = u >> 4, g = u & 15;
        int ii = iy + 1;
        int j0 = 4 * g + 2;

        float2 ca = *(const float2*)&smg[ii][j0];
        float2 cb = *(const float2*)&smg[ii][j0 + 2];
        uchar2 ka = *(const uchar2*)&scl[ii][j0];
        uchar2 kb = *(const uchar2*)&scl[ii][j0 + 2];
        float mcv[4] = {ca.x, ca.y, cb.x, cb.y};
        int   cls[4] = {ka.x, ka.y, kb.x, kb.y};

        float4 res;
        float* rp = &res.x;
        #pragma unroll
        for (int t = 0; t < 4; t++) {
            int s  = cls[t] * 4;
            int dy = (int)((DY >> s) & 0xFu) - 1;
            int dx = (int)((DX >> s) & 0xFu) - 1;
            int jj = j0 + t;
            float mp = smg[ii + dy][jj + dx];
            float mq = smg[ii - dy][jj - dx];
            if (border) {
                int ay = by0 + iy, ax = bx0 + 4 * g + t;
                if (!((unsigned)(ay + dy) < 512u && (unsigned)(ax + dx) < 512u)) mp = 0.0f;
                if (!((unsigned)(ay - dy) < 512u && (unsigned)(ax - dx) < 512u)) mq = 0.0f;
            }
            float m = mcv[t];
            // compare squares: exactly equivalent to comparing magnitudes
            rp[t] = (m > mp && m > mq) ? fast_sqrt(m) : 0.0f;
        }
        *(float4*)&out[((size_t)blockIdx.z * 512 + by0 + iy) * 512 + bx0 + 4 * g] = res;
    }
}

extern "C" void kernel_launch(void* const* d_in, const int* in_sizes, int n_in,
                              void* d_out, int out_size)
{
    (void)in_sizes; (void)n_in; (void)out_size;
    const float* data = (const float*)d_in[0];
    float* out = (float*)d_out;

    dim3 grid(8, 16, 16);
    dim3 block(NT);
    canny_fused_kernel<<<grid, block>>>(data, out);
}

// round 10
// speedup vs baseline: 1.0770x; 1.0110x over previous
#include <cuda_runtime.h>

#define NT 256

__device__ __forceinline__ int reflect512(int i) {
    i = (i < 0) ? -i : i;
    return (i > 511) ? 1022 - i : i;
}
__device__ __forceinline__ int clamp511(int i) {
    return min(max(i, 0), 511);
}
__device__ __forceinline__ float grayf(const float* __restrict__ base, int off) {
    float r = base[off], g = base[off + 262144], b = base[off + 524288];
    return fmaf(0.1495f, r, fmaf(0.2935f, g, fmaf(0.057f, b, 0.5f)));
}
__device__ __forceinline__ int octclass(float gx, float gy) {
    const float T = 0.41421356237309503f;  // tan(22.5 deg)
    float ax = fabsf(gx), ay = fabsf(gy);
    if (ay <= T * ax) return 0;
    if (ax <= T * ay) return 2;
    return ((__float_as_int(gx) ^ __float_as_int(gy)) >= 0) ? 1 : 3;
}
// sqrt without MUFU: bit-hack rsqrt + 2 Newton iterations. x >= 1e-6 always.
__device__ __forceinline__ float fast_sqrt(float x) {
    float y = __int_as_float(0x5f3759df - (__float_as_int(x) >> 1));
    y = y * fmaf(-0.5f * x, y * y, 1.5f);
    y = y * fmaf(-0.5f * x, y * y, 1.5f);
    return x * y;
}
__device__ __forceinline__ float4 hblur4(float4 v0, float4 v1,
                                         float w0, float w1, float w2) {
    float4 o;
    o.x = w0 * (v0.x + v1.x) + w1 * (v0.y + v0.w) + w2 * v0.z;
    o.y = w0 * (v0.y + v1.y) + w1 * (v0.z + v1.x) + w2 * v0.w;
    o.z = w0 * (v0.z + v1.z) + w1 * (v0.w + v1.y) + w2 * v1.x;
    o.w = w0 * (v0.w + v1.w) + w1 * (v1.x + v1.z) + w2 * v1.y;
    return o;
}

struct Row6 { float m, x, y, z, w, p; };

__device__ __forceinline__ void sobel_row(const Row6& a, const Row6& b, const Row6& c,
                                          float4& mg, uchar4& cc) {
    {
        float gx = (a.y - a.m) + 2.0f * (b.y - b.m) + (c.y - c.m);
        float gy = (c.m - a.m) + 2.0f * (c.x - a.x) + (c.y - a.y);
        mg.x = fmaf(gx, gx, fmaf(gy, gy, 1e-6f)); cc.x = (unsigned char)octclass(gx, gy);
    }
    {
        float gx = (a.z - a.x) + 2.0f * (b.z - b.x) + (c.z - c.x);
        float gy = (c.x - a.x) + 2.0f * (c.y - a.y) + (c.z - a.z);
        mg.y = fmaf(gx, gx, fmaf(gy, gy, 1e-6f)); cc.y = (unsigned char)octclass(gx, gy);
    }
    {
        float gx = (a.w - a.y) + 2.0f * (b.w - b.y) + (c.w - c.y);
        float gy = (c.y - a.y) + 2.0f * (c.z - a.z) + (c.w - a.w);
        mg.z = fmaf(gx, gx, fmaf(gy, gy, 1e-6f)); cc.z = (unsigned char)octclass(gx, gy);
    }
    {
        float gx = (a.p - a.z) + 2.0f * (b.p - b.z) + (c.p - c.z);
        float gy = (c.z - a.z) + 2.0f * (c.w - a.w) + (c.p - a.p);
        mg.w = fmaf(gx, gx, fmaf(gy, gy, 1e-6f)); cc.w = (unsigned char)octclass(gx, gy);
    }
}

__global__ __launch_bounds__(NT)
void canny_fused_kernel(const float* __restrict__ in, float* __restrict__ out)
{
    // 64x32 output tile. Row stride 76 floats (rows 16B aligned).
    //   poolA: sg[40][76] (gray, cols 0..71) -> sb[36][76] (vblur, cols 0..67)
    //   poolB: th[40][76] (hblur, cols 0..67) -> smg[34][76] (squared mag, cols 1..66)
    __shared__ __align__(16) float poolA[40 * 76];
    __shared__ __align__(16) float poolB[40 * 76];
    __shared__ __align__(16) unsigned char sclbuf[34 * 76];

    float (*sg)[76]  = reinterpret_cast<float(*)[76]>(poolA);
    float (*sb)[76]  = reinterpret_cast<float(*)[76]>(poolA);
    float (*th)[76]  = reinterpret_cast<float(*)[76]>(poolB);
    float (*smg)[76] = reinterpret_cast<float(*)[76]>(poolB);
    unsigned char (*scl)[76] = reinterpret_cast<unsigned char(*)[76]>(sclbuf);

    const int tid = threadIdx.x;
    const int bx0 = blockIdx.x * 64, by0 = blockIdx.y * 32;
    const float* base = in + (size_t)blockIdx.z * 786432u;
    const float w0 = 0.054488685f, w1 = 0.24420134f, w2 = 0.40261995f;

    const bool reflX = (blockIdx.x == 0u) | (blockIdx.x == 7u);
    const bool reflY = (blockIdx.y == 0u) | (blockIdx.y == 15u);

    // ---- stage 1: gray, 20 row-pairs x 18 groups = 360 items ----
    if (!(reflX | reflY)) {
        #pragma unroll
        for (int k = 0; k < 2; k++) {
            int u = tid + k * NT;
            if (u < 360) {
                int pr = u / 18, g = u - pr * 18;
                int ly = 2 * pr;
                int off = (by0 - 4 + ly) * 512 + (bx0 - 4) + 4 * g;
                #pragma unroll
                for (int rr = 0; rr < 2; rr++) {
                    float4 r  = *(const float4*)(base + off);
                    float4 gg = *(const float4*)(base + off + 262144);
                    float4 bb = *(const float4*)(base + off + 524288);
                    float4 o;
                    o.x = fmaf(0.1495f, r.x, fmaf(0.2935f, gg.x, fmaf(0.057f, bb.x, 0.5f)));
                    o.y = fmaf(0.1495f, r.y, fmaf(0.2935f, gg.y, fmaf(0.057f, bb.y, 0.5f)));
                    o.z = fmaf(0.1495f, r.z, fmaf(0.2935f, gg.z, fmaf(0.057f, bb.z, 0.5f)));
                    o.w = fmaf(0.1495f, r.w, fmaf(0.2935f, gg.w, fmaf(0.057f, bb.w, 0.5f)));
                    *(float4*)&sg[ly + rr][4 * g] = o;
                    off += 512;
                }
            }
        }
    } else {
        for (int u = tid; u < 40 * 72; u += NT) {
            int ly = u / 72, lx = u - ly * 72;
            int ay = by0 - 4 + ly, ax = bx0 - 4 + lx;
            float g = 0.0f;
            if ((unsigned)ay < 512u && (unsigned)ax < 512u) g = grayf(base, ay * 512 + ax);
            sg[ly][lx] = g;
        }
    }
    __syncthreads();

    // ---- stage 2: horizontal blur, 20 row-pairs x 18 groups = 360 items ----
    if (!reflX) {
        #pragma unroll
        for (int k = 0; k < 2; k++) {
            int u = tid + k * NT;
            if (u < 360) {
                int pr = u / 18, g = u - pr * 18;
                int ly = 2 * pr;
                float4 a0 = *(const float4*)&sg[ly][4 * g];
                float4 a1 = *(const float4*)&sg[ly][4 * g + 4];
                float4 b0 = *(const float4*)&sg[ly + 1][4 * g];
                float4 b1 = *(const float4*)&sg[ly + 1][4 * g + 4];
                *(float4*)&th[ly][4 * g]     = hblur4(a0, a1, w0, w1, w2);
                *(float4*)&th[ly + 1][4 * g] = hblur4(b0, b1, w0, w1, w2);
            }
        }
    } else {
        const int ox = bx0 - 4;
        for (int u = tid; u < 40 * 68; u += NT) {
            int ly = u / 68, j = u - ly * 68;
            int cx = clamp511(bx0 - 2 + j);
            th[ly][j] = w0 * (sg[ly][reflect512(cx - 2) - ox] + sg[ly][reflect512(cx + 2) - ox])
                      + w1 * (sg[ly][reflect512(cx - 1) - ox] + sg[ly][reflect512(cx + 1) - ox])
                      + w2 * sg[ly][reflect512(cx) - ox];
        }
    }
    __syncthreads();

    // ---- stage 3: vertical blur -> sb rows 0..35; 18 row-pairs x 18 groups = 324 items ----
    #pragma unroll
    for (int k = 0; k < 2; k++) {
        int u = tid + k * NT;
        if (u < 324) {
            int pr = u / 18, g = u - pr * 18;
            int i = 2 * pr;
            if (!reflY) {
                float4 a = *(const float4*)&th[i    ][4 * g];
                float4 b = *(const float4*)&th[i + 1][4 * g];
                float4 c = *(const float4*)&th[i + 2][4 * g];
                float4 d = *(const float4*)&th[i + 3][4 * g];
                float4 e = *(const float4*)&th[i + 4][4 * g];
                float4 f = *(const float4*)&th[i + 5][4 * g];
                float4 o0, o1;
                o0.x = w0 * (a.x + e.x) + w1 * (b.x + d.x) + w2 * c.x;
                o0.y = w0 * (a.y + e.y) + w1 * (b.y + d.y) + w2 * c.y;
                o0.z = w0 * (a.z + e.z) + w1 * (b.z + d.z) + w2 * c.z;
                o0.w = w0 * (a.w + e.w) + w1 * (b.w + d.w) + w2 * c.w;
                o1.x = w0 * (b.x + f.x) + w1 * (c.x + e.x) + w2 * d.x;
                o1.y = w0 * (b.y + f.y) + w1 * (c.y + e.y) + w2 * d.y;
                o1.z = w0 * (b.z + f.z) + w1 * (c.z + e.z) + w2 * d.z;
                o1.w = w0 * (b.w + f.w) + w1 * (c.w + e.w) + w2 * d.w;
                *(float4*)&sb[i][4 * g]     = o0;
                *(float4*)&sb[i + 1][4 * g] = o1;
            } else {
                #pragma unroll
                for (int rr = 0; rr < 2; rr++) {
                    int ir = i + rr;
                    int cy = clamp511(by0 - 2 + ir), oy = by0 - 4;
                    int r0 = reflect512(cy - 2) - oy, r1 = reflect512(cy - 1) - oy;
                    int r2 = reflect512(cy) - oy;
                    int r3 = reflect512(cy + 1) - oy, r4 = reflect512(cy + 2) - oy;
                    float4 a = *(const float4*)&th[r0][4 * g];
                    float4 b = *(const float4*)&th[r1][4 * g];
                    float4 c = *(const float4*)&th[r2][4 * g];
                    float4 d = *(const float4*)&th[r3][4 * g];
                    float4 e = *(const float4*)&th[r4][4 * g];
                    float4 o;
                    o.x = w0 * (a.x + e.x) + w1 * (b.x + d.x) + w2 * c.x;
                    o.y = w0 * (a.y + e.y) + w1 * (b.y + d.y) + w2 * c.y;
                    o.z = w0 * (a.z + e.z) + w1 * (b.z + d.z) + w2 * c.z;
                    o.w = w0 * (a.w + e.w) + w1 * (b.w + d.w) + w2 * c.w;
                    *(float4*)&sb[ir][4 * g] = o;
                }
            }
        }
    }
    __syncthreads();

    // ---- stage 4: Sobel + squared mag + class; 17 row-pairs x 18 groups = 306 items ----
    #pragma unroll
    for (int k = 0; k < 2; k++) {
        int u = tid + k * NT;
        if (u < 306) {
            int pr = u / 18, g = u - pr * 18;
            int i = 2 * pr;
            int cm = max(4 * g - 1, 0);
            Row6 r[4];
            #pragma unroll
            for (int rr = 0; rr < 4; rr++) {
                const float* row = &sb[i + rr][0];
                float4 v = *(const float4*)&row[4 * g];
                r[rr].m = row[cm]; r[rr].x = v.x; r[rr].y = v.y;
                r[rr].z = v.z;     r[rr].w = v.w; r[rr].p = row[4 * g + 4];
            }
            float4 mgA, mgB; uchar4 ccA, ccB;
            sobel_row(r[0], r[1], r[2], mgA, ccA);
            sobel_row(r[1], r[2], r[3], mgB, ccB);
            *(float4*)&smg[i][4 * g]     = mgA;
            *(uchar4*)&scl[i][4 * g]     = ccA;
            *(float4*)&smg[i + 1][4 * g] = mgB;
            *(uchar4*)&scl[i + 1][4 * g] = ccB;
        }
    }
    __syncthreads();

    // ---- stage 5: NMS on squared magnitudes + fast_sqrt; 512 items ----
    const unsigned DY = 0x0001u, DX = 0x0122u;
    const bool border = reflX | reflY;

    #pragma unroll
    for (int k = 0; k < 2; k++) {
        int u = tid + k * NT;
        int iy = u >> 4, g = u & 15;
        int ii = iy + 1;
        int j0 = 4 * g + 2;

        float2 ca = *(const float2*)&smg[ii][j0];
        float2 cb = *(const float2*)&smg[ii][j0 + 2];
        uchar2 ka = *(const uchar2*)&scl[ii][j0];
        uchar2 kb = *(const uchar2*)&scl[ii][j0 + 2];
        float mcv[4] = {ca.x, ca.y, cb.x, cb.y};
        int   cls[4] = {ka.x, ka.y, kb.x, kb.y};

        float4 res;
        float* rp = &res.x;
        #pragma unroll
        for (int t = 0; t < 4; t++) {
            int s  = cls[t] * 4;
            int dy = (int)((DY >> s) & 0xFu) - 1;
            int dx = (int)((DX >> s) & 0xFu) - 1;
            int jj = j0 + t;
            float mp = smg[ii + dy][jj + dx];
            float mq = smg[ii - dy][jj - dx];
            if (border) {
                int ay = by0 + iy, ax = bx0 + 4 * g + t;
                if (!((unsigned)(ay + dy) < 512u && (unsigned)(ax + dx) < 512u)) mp = 0.0f;
                if (!((unsigned)(ay - dy) < 512u && (unsigned)(ax - dx) < 512u)) mq = 0.0f;
            }
            float m = mcv[t];
            rp[t] = (m > mp && m > mq) ? fast_sqrt(m) : 0.0f;
        }
        *(float4*)&out[((size_t)blockIdx.z * 512 + by0 + iy) * 512 + bx0 + 4 * g] = res;
    }
}

extern "C" void kernel_launch(void* const* d_in, const int* in_sizes, int n_in,
                              void* d_out, int out_size)
{
    (void)in_sizes; (void)n_in; (void)out_size;
    const float* data = (const float*)d_in[0];
    float* out = (float*)d_out;

    dim3 grid(8, 16, 16);
    dim3 block(NT);
    canny_fused_kernel<<<grid, block>>>(data, out);
}